// round 14
// baseline (speedup 1.0000x reference)
#include <cuda_runtime.h>
#include <cuda_bf16.h>
#include <cstdint>

#define NN   4096
#define DD   16
#define CC   1024

// ---- GEMM tiling (R8/R13-proven, byte-for-byte) ----
#define BM 128
#define BN 128
#define STAGES 4
#define KTILES 128            // K=4096 / BK=32
#define ASTG 8192             // A stage: 128 m-rows x 64 B
#define BSTG 8192             // B stage: 32 k-rows x 256 B
#define STGB (ASTG + BSTG)    // 16 KB
#define PIPE_B (STAGES*STGB)  // 64 KB
#define STAGE_PAD 129
#define EPI_B (128*STAGE_PAD*4)
#define DSMEM (EPI_B > PIPE_B ? EPI_B : PIPE_B)

// ---- scratch ----
__device__ float          g_Hf0[(size_t)NN*CC];
__device__ float          g_Hf1[(size_t)NN*CC];
__device__ __nv_bfloat16  g_Hb0[(size_t)NN*CC];
__device__ __nv_bfloat16  g_Hb1[(size_t)NN*CC];
__device__ __nv_bfloat16  g_adjb[(size_t)NN*NN];

__device__ __forceinline__ uint32_t smem_u32(const void* p) {
    uint32_t a;
    asm("{ .reg .u64 t; cvta.to.shared.u64 t, %1; cvt.u32.u64 %0, t; }" : "=r"(a) : "l"(p));
    return a;
}
__device__ __forceinline__ void cp16(uint32_t dst, const void* src) {
    asm volatile("cp.async.cg.shared.global [%0], [%1], 16;" :: "r"(dst), "l"(src) : "memory");
}
__device__ __forceinline__ uint32_t swzA(int r, int q) {
    return (uint32_t)((r << 6) + ((q ^ ((r >> 1) & 3)) << 4));
}
__device__ __forceinline__ uint32_t swzB(int k, int q) {
    return (uint32_t)((k << 8) + ((q ^ (k & 7)) << 4));
}

#define LDSM4(R, addr) \
    asm volatile("ldmatrix.sync.aligned.m8n8.x4.shared.b16 {%0,%1,%2,%3}, [%4];" \
        : "=r"((R)[0]), "=r"((R)[1]), "=r"((R)[2]), "=r"((R)[3]) : "r"(addr))
#define LDSM4T(R, addr) \
    asm volatile("ldmatrix.sync.aligned.m8n8.x4.trans.shared.b16 {%0,%1,%2,%3}, [%4];" \
        : "=r"((R)[0]), "=r"((R)[1]), "=r"((R)[2]), "=r"((R)[3]) : "r"(addr))

#define MMA(C, A_, B0, B1) \
    asm volatile("mma.sync.aligned.m16n8k16.row.col.f32.bf16.bf16.f32 " \
        "{%0,%1,%2,%3}, {%4,%5,%6,%7}, {%8,%9}, {%0,%1,%2,%3};" \
        : "+f"((C)[0]), "+f"((C)[1]), "+f"((C)[2]), "+f"((C)[3]) \
        : "r"((A_)[0]), "r"((A_)[1]), "r"((A_)[2]), "r"((A_)[3]), "r"(B0), "r"(B1))

// ===== fused0: blocks [0,1024): adj cvt (MLP=16, streaming); [1024,5120): lin layer0 =====
__global__ __launch_bounds__(256)
void fused0_kernel(const float* __restrict__ adj, __nv_bfloat16* __restrict__ Ab,
                   const float* __restrict__ X, const float* __restrict__ W,
                   float* __restrict__ Hf, __nv_bfloat16* __restrict__ Hb) {
    __shared__ float sW[DD][DD];
    __shared__ float sX[2][32][DD];
    const int t = threadIdx.x;

    if (blockIdx.x < 1024) {
        // ---- cvt adj: 8 uint4 outputs per thread, block-strided, streaming loads ----
        const size_t base = (size_t)blockIdx.x * 2048 + t;   // uint4 index
        const float4* src = reinterpret_cast<const float4*>(adj);
        float4 v[16];
#pragma unroll
        for (int j = 0; j < 8; j++) {
            v[2*j]   = __ldcs(&src[(base + j * 256) * 2]);
            v[2*j+1] = __ldcs(&src[(base + j * 256) * 2 + 1]);
        }
#pragma unroll
        for (int j = 0; j < 8; j++) {
            union { __nv_bfloat162 h[4]; uint4 u4; } pk;
            pk.h[0] = __floats2bfloat162_rn(v[2*j].x,   v[2*j].y);
            pk.h[1] = __floats2bfloat162_rn(v[2*j].z,   v[2*j].w);
            pk.h[2] = __floats2bfloat162_rn(v[2*j+1].x, v[2*j+1].y);
            pk.h[3] = __floats2bfloat162_rn(v[2*j+1].z, v[2*j+1].w);
            reinterpret_cast<uint4*>(Ab)[base + j * 256] = pk.u4;
        }
        return;
    }
    const int bid = blockIdx.x - 1024;
    const int c0 = (bid & 31) * 32, m0 = (bid >> 5) * 32, b0 = c0 >> 4;

    sW[t >> 4][t & 15] = W[t];
    {
        int bloc = t >> 7, m = (t >> 2) & 31, seg = t & 3;
        const float* xp = X + ((size_t)(b0 + bloc) * NN + (m0 + m)) * DD + seg * 4;
        float4 v = __ldcs(reinterpret_cast<const float4*>(xp));
        sX[bloc][m][seg*4]   = v.x; sX[bloc][m][seg*4+1] = v.y;
        sX[bloc][m][seg*4+2] = v.z; sX[bloc][m][seg*4+3] = v.w;
    }
    __syncthreads();
    {
        int m = t >> 3, quad = t & 7;
        int bloc = quad >> 2;
        int e0 = (quad & 3) * 4;
        float h[4] = {0.f, 0.f, 0.f, 0.f};
#pragma unroll
        for (int d = 0; d < DD; d++) {
            float xd = sX[bloc][m][d];
#pragma unroll
            for (int j = 0; j < 4; j++) h[j] = fmaf(xd, sW[d][e0 + j], h[j]);
        }
#pragma unroll
        for (int j = 0; j < 4; j++) h[j] = h[j] > 0.f ? h[j] : 0.2f * h[j];

        size_t off = (size_t)(m0 + m) * CC + c0 + quad * 4;
        *reinterpret_cast<float4*>(Hf + off) = make_float4(h[0], h[1], h[2], h[3]);
        union { __nv_bfloat162 p[2]; uint2 u; } pk;
        pk.p[0] = __floats2bfloat162_rn(h[0], h[1]);
        pk.p[1] = __floats2bfloat162_rn(h[2], h[3]);
        *reinterpret_cast<uint2*>(Hb + off) = pk.u;
    }
}

// ===== GEMM + fused next-layer linear (exact R8/R13) =====
__global__ __launch_bounds__(128, 2)
void gemm_fused_kernel(const __nv_bfloat16* __restrict__ Ab,
                       const __nv_bfloat16* __restrict__ Hb_in,
                       const float* __restrict__ Hf_in,
                       const float* __restrict__ Wn,
                       float* __restrict__ Hf_out,
                       __nv_bfloat16* __restrict__ Hb_out,
                       float* __restrict__ Dout,
                       int final_layer) {
    extern __shared__ char dsm[];
    __shared__ float sW[DD][DD + 1];
    const uint32_t sm = smem_u32(dsm);
    const int tid = threadIdx.x, wid = tid >> 5, l = tid & 31;
    const int bx = blockIdx.x, by = blockIdx.y;
    const int wm = wid >> 1, wn = wid & 1;

    if (!final_layer) {
        sW[tid >> 4][tid & 15] = Wn[tid & 255];
        if (tid < 128) sW[(tid + 128) >> 4][tid & 15] = Wn[128 + (tid & 127)];
    }

    const char* gA = (const char*)(Ab + (size_t)by * BM * NN);
    const char* gB = (const char*)Hb_in + (size_t)bx * BN * 2;

    const int rA = tid >> 2, qA = tid & 3;
    uint32_t offA[4]; size_t gOffA[4];
#pragma unroll
    for (int i = 0; i < 4; i++) {
        offA[i]  = swzA(rA + 32 * i, qA);
        gOffA[i] = (size_t)(rA + 32 * i) * 8192 + qA * 16;
    }
    uint32_t offB[4]; int kB[4], qB[4];
#pragma unroll
    for (int i = 0; i < 4; i++) {
        int idx = i * 128 + tid;
        kB[i] = idx >> 4; qB[i] = idx & 15;
        offB[i] = swzB(kB[i], qB[i]);
    }

#define LOAD_STAGE(s, kt) { \
    uint32_t sa = sm + (uint32_t)(s) * STGB; \
    const char* ga = gA + (size_t)(kt) * 64; \
    _Pragma("unroll") \
    for (int i_ = 0; i_ < 4; i_++) cp16(sa + offA[i_], ga + gOffA[i_]); \
    uint32_t sb = sa + ASTG; \
    const char* gb = gB + (size_t)(kt) * 32 * 2048; \
    _Pragma("unroll") \
    for (int i_ = 0; i_ < 4; i_++) \
        cp16(sb + offB[i_], gb + (size_t)kB[i_] * 2048 + qB[i_] * 16); }

    const int arow = wm * 64 + (l & 15);
    const int aqh  = l >> 4;
    const int g    = l >> 3;
    const int bk   = (g & 1) * 8 + (l & 7);
    const int bq   = wn * 8 + (g >> 1);

    float acc[4][8][4];
#pragma unroll
    for (int i = 0; i < 4; i++)
#pragma unroll
        for (int j = 0; j < 8; j++)
#pragma unroll
            for (int k = 0; k < 4; k++) acc[i][j][k] = 0.0f;

#pragma unroll
    for (int s = 0; s < STAGES - 1; s++) {
        LOAD_STAGE(s, s);
        asm volatile("cp.async.commit_group;" ::: "memory");
    }
    asm volatile("cp.async.wait_group %0;" :: "n"(STAGES - 2) : "memory");
    __syncthreads();

    uint32_t a[2][4][4], b[2][4][4];

#pragma unroll 1
    for (int kt = 0; kt < KTILES; kt++) {
        int pf = kt + STAGES - 1;
        if (pf < KTILES) { LOAD_STAGE(pf & (STAGES - 1), pf); }
        asm volatile("cp.async.commit_group;" ::: "memory");

        const uint32_t base  = sm + (uint32_t)(kt & (STAGES - 1)) * STGB;
        const uint32_t baseB = base + ASTG;

#pragma unroll
        for (int mi = 0; mi < 4; mi++)
            LDSM4(a[0][mi], base + swzA(arow + mi * 16, aqh));
#pragma unroll
        for (int nb = 0; nb < 4; nb++)
            LDSM4T(b[0][nb], baseB + swzB(bk, bq + nb * 2));

#pragma unroll
        for (int ks = 0; ks < 2; ks++) {
            if (ks == 0) {
#pragma unroll
                for (int mi = 0; mi < 4; mi++)
                    LDSM4(a[1][mi], base + swzA(arow + mi * 16, 2 + aqh));
#pragma unroll
                for (int nb = 0; nb < 4; nb++)
                    LDSM4T(b[1][nb], baseB + swzB(16 + bk, bq + nb * 2));
            }
#pragma unroll
            for (int mi = 0; mi < 4; mi++) {
#pragma unroll
                for (int nb = 0; nb < 4; nb++) {
                    const uint32_t* bb = b[ks][nb];
                    MMA(acc[mi][2*nb],   a[ks][mi], bb[0], bb[1]);
                    MMA(acc[mi][2*nb+1], a[ks][mi], bb[2], bb[3]);
                }
            }
        }
        asm volatile("cp.async.wait_group %0;" :: "n"(STAGES - 2) : "memory");
        __syncthreads();
    }
    asm volatile("cp.async.wait_group 0;" ::: "memory");
    __syncthreads();

    // ==== epilogue ====
    const int m0g = by * BM, c0g = bx * BN;

    if (final_layer) {
#pragma unroll
        for (int mi = 0; mi < 4; mi++) {
#pragma unroll
            for (int ni = 0; ni < 8; ni++) {
                int m = m0g + wm * 64 + mi * 16 + (l >> 2);
                int c = c0g + wn * 64 + ni * 8 + 2 * (l & 3);
                float2 i0 = *reinterpret_cast<const float2*>(Hf_in + (size_t)m * CC + c);
                float2 i1 = *reinterpret_cast<const float2*>(Hf_in + (size_t)(m + 8) * CC + c);
                float2 o0 = make_float2(acc[mi][ni][0] + i0.x, acc[mi][ni][1] + i0.y);
                float2 o1 = make_float2(acc[mi][ni][2] + i1.x, acc[mi][ni][3] + i1.y);
                int bq2 = c >> 4, d = c & 15;
                *reinterpret_cast<float2*>(Dout + ((size_t)bq2 * NN + m) * DD + d) = o0;
                *reinterpret_cast<float2*>(Dout + ((size_t)bq2 * NN + m + 8) * DD + d) = o1;
            }
        }
        return;
    }

    // stage o = acc + identity into smem [c][m] (pad 129)
    float* stage = reinterpret_cast<float*>(dsm);
#pragma unroll
    for (int mi = 0; mi < 4; mi++) {
#pragma unroll
        for (int ni = 0; ni < 8; ni++) {
            int mloc = wm * 64 + mi * 16 + (l >> 2);
            int cloc = wn * 64 + ni * 8 + 2 * (l & 3);
            int m = m0g + mloc, c = c0g + cloc;
            float2 i0 = *reinterpret_cast<const float2*>(Hf_in + (size_t)m * CC + c);
            float2 i1 = *reinterpret_cast<const float2*>(Hf_in + (size_t)(m + 8) * CC + c);
            stage[cloc * STAGE_PAD + mloc]           = acc[mi][ni][0] + i0.x;
            stage[(cloc + 1) * STAGE_PAD + mloc]     = acc[mi][ni][1] + i0.y;
            stage[cloc * STAGE_PAD + mloc + 8]       = acc[mi][ni][2] + i1.x;
            stage[(cloc + 1) * STAGE_PAD + mloc + 8] = acc[mi][ni][3] + i1.y;
        }
    }
    __syncthreads();

    // next-layer linear
    {
        const int bgrp = tid >> 4, mlane = tid & 15;
#pragma unroll
        for (int it = 0; it < 8; it++) {
            int mloc = mlane + 16 * it;
            float o[16];
#pragma unroll
            for (int d = 0; d < 16; d++)
                o[d] = stage[(bgrp * 16 + d) * STAGE_PAD + mloc];
            float h[16];
#pragma unroll
            for (int e = 0; e < 16; e++) h[e] = 0.0f;
#pragma unroll
            for (int d = 0; d < 16; d++) {
                float od = o[d];
#pragma unroll
                for (int e = 0; e < 16; e++) h[e] = fmaf(od, sW[d][e], h[e]);
            }
#pragma unroll
            for (int e = 0; e < 16; e++) h[e] = h[e] > 0.f ? h[e] : 0.2f * h[e];

            size_t off = (size_t)(m0g + mloc) * CC + c0g + bgrp * 16;
#pragma unroll
            for (int j = 0; j < 4; j++)
                *reinterpret_cast<float4*>(Hf_out + off + j * 4) =
                    make_float4(h[4*j], h[4*j+1], h[4*j+2], h[4*j+3]);
            union { __nv_bfloat162 p[4]; uint4 u; } pk;
#pragma unroll
            for (int j = 0; j < 4; j++) pk.p[j] = __floats2bfloat162_rn(h[2*j], h[2*j+1]);
            *reinterpret_cast<uint4*>(Hb_out + off) = pk.u;
#pragma unroll
            for (int j = 0; j < 4; j++) pk.p[j] = __floats2bfloat162_rn(h[8+2*j], h[9+2*j]);
            *reinterpret_cast<uint4*>(Hb_out + off + 8) = pk.u;
        }
    }
#undef LOAD_STAGE
}

// ================= launch =================
extern "C" void kernel_launch(void* const* d_in, const int* in_sizes, int n_in,
                              void* d_out, int out_size) {
    const float* x   = (const float*)d_in[0];
    const float* adj = (const float*)d_in[1];
    const float* W0  = (const float*)d_in[3];
    const float* W1  = (const float*)d_in[4];
    const float* W2  = (const float*)d_in[5];
    float* out = (float*)d_out;

    float *pHf0, *pHf1;
    __nv_bfloat16 *pHb0, *pHb1, *pAb;
    cudaGetSymbolAddress((void**)&pHf0, g_Hf0);
    cudaGetSymbolAddress((void**)&pHf1, g_Hf1);
    cudaGetSymbolAddress((void**)&pHb0, g_Hb0);
    cudaGetSymbolAddress((void**)&pHb1, g_Hb1);
    cudaGetSymbolAddress((void**)&pAb,  g_adjb);

    cudaFuncSetAttribute(gemm_fused_kernel, cudaFuncAttributeMaxDynamicSharedMemorySize, DSMEM);

    dim3 ggrid(CC / BN, NN / BM);                  // (8, 32) = 256 CTAs

    fused0_kernel<<<5120, 256>>>(adj, pAb, x, W0, pHf0, pHb0);
    gemm_fused_kernel<<<ggrid, 128, DSMEM>>>(pAb, pHb0, pHf0, W1, pHf1, pHb1, nullptr, 0);
    gemm_fused_kernel<<<ggrid, 128, DSMEM>>>(pAb, pHb1, pHf1, W2, pHf0, pHb0, nullptr, 0);
    gemm_fused_kernel<<<ggrid, 128, DSMEM>>>(pAb, pHb0, pHf0, nullptr, nullptr, nullptr, out, 1);
}

// round 15
// speedup vs baseline: 1.0003x; 1.0003x over previous
#include <cuda_runtime.h>
#include <cuda_bf16.h>
#include <cstdint>

#define NN   4096
#define DD   16
#define CC   1024

// ---- GEMM tiling (R8/R13-proven, byte-for-byte) ----
#define BM 128
#define BN 128
#define STAGES 4
#define KTILES 128            // K=4096 / BK=32
#define ASTG 8192             // A stage: 128 m-rows x 64 B
#define BSTG 8192             // B stage: 32 k-rows x 256 B
#define STGB (ASTG + BSTG)    // 16 KB
#define PIPE_B (STAGES*STGB)  // 64 KB
#define STAGE_PAD 129
#define EPI_B (128*STAGE_PAD*4)
#define DSMEM (EPI_B > PIPE_B ? EPI_B : PIPE_B)

// ---- scratch ----
__device__ float          g_Hf0[(size_t)NN*CC];
__device__ float          g_Hf1[(size_t)NN*CC];
__device__ __nv_bfloat16  g_Hb0[(size_t)NN*CC];
__device__ __nv_bfloat16  g_Hb1[(size_t)NN*CC];
__device__ __nv_bfloat16  g_adjb[(size_t)NN*NN];

__device__ __forceinline__ uint32_t smem_u32(const void* p) {
    uint32_t a;
    asm("{ .reg .u64 t; cvta.to.shared.u64 t, %1; cvt.u32.u64 %0, t; }" : "=r"(a) : "l"(p));
    return a;
}
__device__ __forceinline__ void cp16(uint32_t dst, const void* src) {
    asm volatile("cp.async.cg.shared.global [%0], [%1], 16;" :: "r"(dst), "l"(src) : "memory");
}
__device__ __forceinline__ uint32_t swzA(int r, int q) {
    return (uint32_t)((r << 6) + ((q ^ ((r >> 1) & 3)) << 4));
}
__device__ __forceinline__ uint32_t swzB(int k, int q) {
    return (uint32_t)((k << 8) + ((q ^ (k & 7)) << 4));
}

#define LDSM4(R, addr) \
    asm volatile("ldmatrix.sync.aligned.m8n8.x4.shared.b16 {%0,%1,%2,%3}, [%4];" \
        : "=r"((R)[0]), "=r"((R)[1]), "=r"((R)[2]), "=r"((R)[3]) : "r"(addr))
#define LDSM4T(R, addr) \
    asm volatile("ldmatrix.sync.aligned.m8n8.x4.trans.shared.b16 {%0,%1,%2,%3}, [%4];" \
        : "=r"((R)[0]), "=r"((R)[1]), "=r"((R)[2]), "=r"((R)[3]) : "r"(addr))

#define MMA(C, A_, B0, B1) \
    asm volatile("mma.sync.aligned.m16n8k16.row.col.f32.bf16.bf16.f32 " \
        "{%0,%1,%2,%3}, {%4,%5,%6,%7}, {%8,%9}, {%0,%1,%2,%3};" \
        : "+f"((C)[0]), "+f"((C)[1]), "+f"((C)[2]), "+f"((C)[3]) \
        : "r"((A_)[0]), "r"((A_)[1]), "r"((A_)[2]), "r"((A_)[3]), "r"(B0), "r"(B1))

// ===== fused0: blocks [0,2048): adj cvt (MLP=8, coalesced); [2048,6144): lin layer0 =====
__global__ __launch_bounds__(256)
void fused0_kernel(const float* __restrict__ adj, __nv_bfloat16* __restrict__ Ab,
                   const float* __restrict__ X, const float* __restrict__ W,
                   float* __restrict__ Hf, __nv_bfloat16* __restrict__ Hb) {
    __shared__ float sW[DD][DD];
    __shared__ float sX[2][32][DD];
    const int t = threadIdx.x;

    if (blockIdx.x < 2048) {
        // ---- cvt adj: 4 uint4 outputs per thread, block-strided (coalesced), MLP=8 ----
        const size_t base = (size_t)blockIdx.x * 1024 + t;   // uint4 index
        const float4* src = reinterpret_cast<const float4*>(adj);
        float4 v[8];
#pragma unroll
        for (int j = 0; j < 4; j++) {
            v[2*j]   = src[(base + j * 256) * 2];
            v[2*j+1] = src[(base + j * 256) * 2 + 1];
        }
#pragma unroll
        for (int j = 0; j < 4; j++) {
            union { __nv_bfloat162 h[4]; uint4 u4; } pk;
            pk.h[0] = __floats2bfloat162_rn(v[2*j].x,   v[2*j].y);
            pk.h[1] = __floats2bfloat162_rn(v[2*j].z,   v[2*j].w);
            pk.h[2] = __floats2bfloat162_rn(v[2*j+1].x, v[2*j+1].y);
            pk.h[3] = __floats2bfloat162_rn(v[2*j+1].z, v[2*j+1].w);
            reinterpret_cast<uint4*>(Ab)[base + j * 256] = pk.u4;
        }
        return;
    }
    const int bid = blockIdx.x - 2048;
    const int c0 = (bid & 31) * 32, m0 = (bid >> 5) * 32, b0 = c0 >> 4;

    sW[t >> 4][t & 15] = W[t];
    {
        int bloc = t >> 7, m = (t >> 2) & 31, seg = t & 3;
        const float* xp = X + ((size_t)(b0 + bloc) * NN + (m0 + m)) * DD + seg * 4;
        float4 v = *reinterpret_cast<const float4*>(xp);
        sX[bloc][m][seg*4]   = v.x; sX[bloc][m][seg*4+1] = v.y;
        sX[bloc][m][seg*4+2] = v.z; sX[bloc][m][seg*4+3] = v.w;
    }
    __syncthreads();
    {
        int m = t >> 3, quad = t & 7;
        int bloc = quad >> 2;
        int e0 = (quad & 3) * 4;
        float h[4] = {0.f, 0.f, 0.f, 0.f};
#pragma unroll
        for (int d = 0; d < DD; d++) {
            float xd = sX[bloc][m][d];
#pragma unroll
            for (int j = 0; j < 4; j++) h[j] = fmaf(xd, sW[d][e0 + j], h[j]);
        }
#pragma unroll
        for (int j = 0; j < 4; j++) h[j] = h[j] > 0.f ? h[j] : 0.2f * h[j];

        size_t off = (size_t)(m0 + m) * CC + c0 + quad * 4;
        *reinterpret_cast<float4*>(Hf + off) = make_float4(h[0], h[1], h[2], h[3]);
        union { __nv_bfloat162 p[2]; uint2 u; } pk;
        pk.p[0] = __floats2bfloat162_rn(h[0], h[1]);
        pk.p[1] = __floats2bfloat162_rn(h[2], h[3]);
        *reinterpret_cast<uint2*>(Hb + off) = pk.u;
    }
}

// ===== GEMM + fused next-layer linear (exact R8/R13) =====
__global__ __launch_bounds__(128, 2)
void gemm_fused_kernel(const __nv_bfloat16* __restrict__ Ab,
                       const __nv_bfloat16* __restrict__ Hb_in,
                       const float* __restrict__ Hf_in,
                       const float* __restrict__ Wn,
                       float* __restrict__ Hf_out,
                       __nv_bfloat16* __restrict__ Hb_out,
                       float* __restrict__ Dout,
                       int final_layer) {
    extern __shared__ char dsm[];
    __shared__ float sW[DD][DD + 1];
    const uint32_t sm = smem_u32(dsm);
    const int tid = threadIdx.x, wid = tid >> 5, l = tid & 31;
    const int bx = blockIdx.x, by = blockIdx.y;
    const int wm = wid >> 1, wn = wid & 1;

    if (!final_layer) {
        sW[tid >> 4][tid & 15] = Wn[tid & 255];
        if (tid < 128) sW[(tid + 128) >> 4][tid & 15] = Wn[128 + (tid & 127)];
    }

    const char* gA = (const char*)(Ab + (size_t)by * BM * NN);
    const char* gB = (const char*)Hb_in + (size_t)bx * BN * 2;

    const int rA = tid >> 2, qA = tid & 3;
    uint32_t offA[4]; size_t gOffA[4];
#pragma unroll
    for (int i = 0; i < 4; i++) {
        offA[i]  = swzA(rA + 32 * i, qA);
        gOffA[i] = (size_t)(rA + 32 * i) * 8192 + qA * 16;
    }
    uint32_t offB[4]; int kB[4], qB[4];
#pragma unroll
    for (int i = 0; i < 4; i++) {
        int idx = i * 128 + tid;
        kB[i] = idx >> 4; qB[i] = idx & 15;
        offB[i] = swzB(kB[i], qB[i]);
    }

#define LOAD_STAGE(s, kt) { \
    uint32_t sa = sm + (uint32_t)(s) * STGB; \
    const char* ga = gA + (size_t)(kt) * 64; \
    _Pragma("unroll") \
    for (int i_ = 0; i_ < 4; i_++) cp16(sa + offA[i_], ga + gOffA[i_]); \
    uint32_t sb = sa + ASTG; \
    const char* gb = gB + (size_t)(kt) * 32 * 2048; \
    _Pragma("unroll") \
    for (int i_ = 0; i_ < 4; i_++) \
        cp16(sb + offB[i_], gb + (size_t)kB[i_] * 2048 + qB[i_] * 16); }

    const int arow = wm * 64 + (l & 15);
    const int aqh  = l >> 4;
    const int g    = l >> 3;
    const int bk   = (g & 1) * 8 + (l & 7);
    const int bq   = wn * 8 + (g >> 1);

    float acc[4][8][4];
#pragma unroll
    for (int i = 0; i < 4; i++)
#pragma unroll
        for (int j = 0; j < 8; j++)
#pragma unroll
            for (int k = 0; k < 4; k++) acc[i][j][k] = 0.0f;

#pragma unroll
    for (int s = 0; s < STAGES - 1; s++) {
        LOAD_STAGE(s, s);
        asm volatile("cp.async.commit_group;" ::: "memory");
    }
    asm volatile("cp.async.wait_group %0;" :: "n"(STAGES - 2) : "memory");
    __syncthreads();

    uint32_t a[2][4][4], b[2][4][4];

#pragma unroll 1
    for (int kt = 0; kt < KTILES; kt++) {
        int pf = kt + STAGES - 1;
        if (pf < KTILES) { LOAD_STAGE(pf & (STAGES - 1), pf); }
        asm volatile("cp.async.commit_group;" ::: "memory");

        const uint32_t base  = sm + (uint32_t)(kt & (STAGES - 1)) * STGB;
        const uint32_t baseB = base + ASTG;

#pragma unroll
        for (int mi = 0; mi < 4; mi++)
            LDSM4(a[0][mi], base + swzA(arow + mi * 16, aqh));
#pragma unroll
        for (int nb = 0; nb < 4; nb++)
            LDSM4T(b[0][nb], baseB + swzB(bk, bq + nb * 2));

#pragma unroll
        for (int ks = 0; ks < 2; ks++) {
            if (ks == 0) {
#pragma unroll
                for (int mi = 0; mi < 4; mi++)
                    LDSM4(a[1][mi], base + swzA(arow + mi * 16, 2 + aqh));
#pragma unroll
                for (int nb = 0; nb < 4; nb++)
                    LDSM4T(b[1][nb], baseB + swzB(16 + bk, bq + nb * 2));
            }
#pragma unroll
            for (int mi = 0; mi < 4; mi++) {
#pragma unroll
                for (int nb = 0; nb < 4; nb++) {
                    const uint32_t* bb = b[ks][nb];
                    MMA(acc[mi][2*nb],   a[ks][mi], bb[0], bb[1]);
                    MMA(acc[mi][2*nb+1], a[ks][mi], bb[2], bb[3]);
                }
            }
        }
        asm volatile("cp.async.wait_group %0;" :: "n"(STAGES - 2) : "memory");
        __syncthreads();
    }
    asm volatile("cp.async.wait_group 0;" ::: "memory");
    __syncthreads();

    // ==== epilogue ====
    const int m0g = by * BM, c0g = bx * BN;

    if (final_layer) {
#pragma unroll
        for (int mi = 0; mi < 4; mi++) {
#pragma unroll
            for (int ni = 0; ni < 8; ni++) {
                int m = m0g + wm * 64 + mi * 16 + (l >> 2);
                int c = c0g + wn * 64 + ni * 8 + 2 * (l & 3);
                float2 i0 = *reinterpret_cast<const float2*>(Hf_in + (size_t)m * CC + c);
                float2 i1 = *reinterpret_cast<const float2*>(Hf_in + (size_t)(m + 8) * CC + c);
                float2 o0 = make_float2(acc[mi][ni][0] + i0.x, acc[mi][ni][1] + i0.y);
                float2 o1 = make_float2(acc[mi][ni][2] + i1.x, acc[mi][ni][3] + i1.y);
                int bq2 = c >> 4, d = c & 15;
                *reinterpret_cast<float2*>(Dout + ((size_t)bq2 * NN + m) * DD + d) = o0;
                *reinterpret_cast<float2*>(Dout + ((size_t)bq2 * NN + m + 8) * DD + d) = o1;
            }
        }
        return;
    }

    // stage o = acc + identity into smem [c][m] (pad 129)
    float* stage = reinterpret_cast<float*>(dsm);
#pragma unroll
    for (int mi = 0; mi < 4; mi++) {
#pragma unroll
        for (int ni = 0; ni < 8; ni++) {
            int mloc = wm * 64 + mi * 16 + (l >> 2);
            int cloc = wn * 64 + ni * 8 + 2 * (l & 3);
            int m = m0g + mloc, c = c0g + cloc;
            float2 i0 = *reinterpret_cast<const float2*>(Hf_in + (size_t)m * CC + c);
            float2 i1 = *reinterpret_cast<const float2*>(Hf_in + (size_t)(m + 8) * CC + c);
            stage[cloc * STAGE_PAD + mloc]           = acc[mi][ni][0] + i0.x;
            stage[(cloc + 1) * STAGE_PAD + mloc]     = acc[mi][ni][1] + i0.y;
            stage[cloc * STAGE_PAD + mloc + 8]       = acc[mi][ni][2] + i1.x;
            stage[(cloc + 1) * STAGE_PAD + mloc + 8] = acc[mi][ni][3] + i1.y;
        }
    }
    __syncthreads();

    // next-layer linear
    {
        const int bgrp = tid >> 4, mlane = tid & 15;
#pragma unroll
        for (int it = 0; it < 8; it++) {
            int mloc = mlane + 16 * it;
            float o[16];
#pragma unroll
            for (int d = 0; d < 16; d++)
                o[d] = stage[(bgrp * 16 + d) * STAGE_PAD + mloc];
            float h[16];
#pragma unroll
            for (int e = 0; e < 16; e++) h[e] = 0.0f;
#pragma unroll
            for (int d = 0; d < 16; d++) {
                float od = o[d];
#pragma unroll
                for (int e = 0; e < 16; e++) h[e] = fmaf(od, sW[d][e], h[e]);
            }
#pragma unroll
            for (int e = 0; e < 16; e++) h[e] = h[e] > 0.f ? h[e] : 0.2f * h[e];

            size_t off = (size_t)(m0g + mloc) * CC + c0g + bgrp * 16;
#pragma unroll
            for (int j = 0; j < 4; j++)
                *reinterpret_cast<float4*>(Hf_out + off + j * 4) =
                    make_float4(h[4*j], h[4*j+1], h[4*j+2], h[4*j+3]);
            union { __nv_bfloat162 p[4]; uint4 u; } pk;
#pragma unroll
            for (int j = 0; j < 4; j++) pk.p[j] = __floats2bfloat162_rn(h[2*j], h[2*j+1]);
            *reinterpret_cast<uint4*>(Hb_out + off) = pk.u;
#pragma unroll
            for (int j = 0; j < 4; j++) pk.p[j] = __floats2bfloat162_rn(h[8+2*j], h[9+2*j]);
            *reinterpret_cast<uint4*>(Hb_out + off + 8) = pk.u;
        }
    }
#undef LOAD_STAGE
}

// ================= launch =================
extern "C" void kernel_launch(void* const* d_in, const int* in_sizes, int n_in,
                              void* d_out, int out_size) {
    const float* x   = (const float*)d_in[0];
    const float* adj = (const float*)d_in[1];
    const float* W0  = (const float*)d_in[3];
    const float* W1  = (const float*)d_in[4];
    const float* W2  = (const float*)d_in[5];
    float* out = (float*)d_out;

    float *pHf0, *pHf1;
    __nv_bfloat16 *pHb0, *pHb1, *pAb;
    cudaGetSymbolAddress((void**)&pHf0, g_Hf0);
    cudaGetSymbolAddress((void**)&pHf1, g_Hf1);
    cudaGetSymbolAddress((void**)&pHb0, g_Hb0);
    cudaGetSymbolAddress((void**)&pHb1, g_Hb1);
    cudaGetSymbolAddress((void**)&pAb,  g_adjb);

    cudaFuncSetAttribute(gemm_fused_kernel, cudaFuncAttributeMaxDynamicSharedMemorySize, DSMEM);

    dim3 ggrid(CC / BN, NN / BM);                  // (8, 32) = 256 CTAs

    fused0_kernel<<<6144, 256>>>(adj, pAb, x, W0, pHf0, pHb0);
    gemm_fused_kernel<<<ggrid, 128, DSMEM>>>(pAb, pHb0, pHf0, W1, pHf1, pHb1, nullptr, 0);
    gemm_fused_kernel<<<ggrid, 128, DSMEM>>>(pAb, pHb1, pHf1, W2, pHf0, pHb0, nullptr, 0);
    gemm_fused_kernel<<<ggrid, 128, DSMEM>>>(pAb, pHb0, pHf0, nullptr, nullptr, nullptr, out, 1);
}

// round 16
// speedup vs baseline: 1.0067x; 1.0064x over previous
#include <cuda_runtime.h>
#include <cuda_bf16.h>
#include <cstdint>

#define NN   4096
#define DD   16
#define CC   1024

// ---- GEMM tiling (R8/R13-proven, byte-for-byte) ----
#define BM 128
#define BN 128
#define STAGES 4
#define KTILES 128            // K=4096 / BK=32
#define ASTG 8192             // A stage: 128 m-rows x 64 B
#define BSTG 8192             // B stage: 32 k-rows x 256 B
#define STGB (ASTG + BSTG)    // 16 KB
#define PIPE_B (STAGES*STGB)  // 64 KB
#define STAGE_PAD 129
#define EPI_B (128*STAGE_PAD*4)
#define DSMEM (EPI_B > PIPE_B ? EPI_B : PIPE_B)

// ---- scratch ----
__device__ float          g_Hf0[(size_t)NN*CC];
__device__ float          g_Hf1[(size_t)NN*CC];
__device__ __nv_bfloat16  g_Hb0[(size_t)NN*CC];
__device__ __nv_bfloat16  g_Hb1[(size_t)NN*CC];
__device__ __nv_bfloat16  g_adjb[(size_t)NN*NN];

__device__ __forceinline__ uint32_t smem_u32(const void* p) {
    uint32_t a;
    asm("{ .reg .u64 t; cvta.to.shared.u64 t, %1; cvt.u32.u64 %0, t; }" : "=r"(a) : "l"(p));
    return a;
}
__device__ __forceinline__ void cp16(uint32_t dst, const void* src) {
    asm volatile("cp.async.cg.shared.global [%0], [%1], 16;" :: "r"(dst), "l"(src) : "memory");
}
__device__ __forceinline__ uint32_t swzA(int r, int q) {
    return (uint32_t)((r << 6) + ((q ^ ((r >> 1) & 3)) << 4));
}
__device__ __forceinline__ uint32_t swzB(int k, int q) {
    return (uint32_t)((k << 8) + ((q ^ (k & 7)) << 4));
}

#define LDSM4(R, addr) \
    asm volatile("ldmatrix.sync.aligned.m8n8.x4.shared.b16 {%0,%1,%2,%3}, [%4];" \
        : "=r"((R)[0]), "=r"((R)[1]), "=r"((R)[2]), "=r"((R)[3]) : "r"(addr))
#define LDSM4T(R, addr) \
    asm volatile("ldmatrix.sync.aligned.m8n8.x4.trans.shared.b16 {%0,%1,%2,%3}, [%4];" \
        : "=r"((R)[0]), "=r"((R)[1]), "=r"((R)[2]), "=r"((R)[3]) : "r"(addr))

#define MMA(C, A_, B0, B1) \
    asm volatile("mma.sync.aligned.m16n8k16.row.col.f32.bf16.bf16.f32 " \
        "{%0,%1,%2,%3}, {%4,%5,%6,%7}, {%8,%9}, {%0,%1,%2,%3};" \
        : "+f"((C)[0]), "+f"((C)[1]), "+f"((C)[2]), "+f"((C)[3]) \
        : "r"((A_)[0]), "r"((A_)[1]), "r"((A_)[2]), "r"((A_)[3]), "r"(B0), "r"(B1))

// ===== fused0: blocks [0,2048): adj cvt (MLP=8, coalesced); [2048,6144): lin layer0 =====
__global__ __launch_bounds__(256)
void fused0_kernel(const float* __restrict__ adj, __nv_bfloat16* __restrict__ Ab,
                   const float* __restrict__ X, const float* __restrict__ W,
                   float* __restrict__ Hf, __nv_bfloat16* __restrict__ Hb) {
    __shared__ float sW[DD][DD];
    __shared__ float sX[2][32][DD];
    const int t = threadIdx.x;

    if (blockIdx.x < 2048) {
        // ---- cvt adj: 4 uint4 outputs per thread, block-strided (coalesced), MLP=8 ----
        const size_t base = (size_t)blockIdx.x * 1024 + t;   // uint4 index
        const float4* src = reinterpret_cast<const float4*>(adj);
        float4 v[8];
#pragma unroll
        for (int j = 0; j < 4; j++) {
            v[2*j]   = src[(base + j * 256) * 2];
            v[2*j+1] = src[(base + j * 256) * 2 + 1];
        }
#pragma unroll
        for (int j = 0; j < 4; j++) {
            union { __nv_bfloat162 h[4]; uint4 u4; } pk;
            pk.h[0] = __floats2bfloat162_rn(v[2*j].x,   v[2*j].y);
            pk.h[1] = __floats2bfloat162_rn(v[2*j].z,   v[2*j].w);
            pk.h[2] = __floats2bfloat162_rn(v[2*j+1].x, v[2*j+1].y);
            pk.h[3] = __floats2bfloat162_rn(v[2*j+1].z, v[2*j+1].w);
            reinterpret_cast<uint4*>(Ab)[base + j * 256] = pk.u4;
        }
        return;
    }
    const int bid = blockIdx.x - 2048;
    const int c0 = (bid & 31) * 32, m0 = (bid >> 5) * 32, b0 = c0 >> 4;

    sW[t >> 4][t & 15] = W[t];
    {
        int bloc = t >> 7, m = (t >> 2) & 31, seg = t & 3;
        const float* xp = X + ((size_t)(b0 + bloc) * NN + (m0 + m)) * DD + seg * 4;
        float4 v = *reinterpret_cast<const float4*>(xp);
        sX[bloc][m][seg*4]   = v.x; sX[bloc][m][seg*4+1] = v.y;
        sX[bloc][m][seg*4+2] = v.z; sX[bloc][m][seg*4+3] = v.w;
    }
    __syncthreads();
    {
        int m = t >> 3, quad = t & 7;
        int bloc = quad >> 2;
        int e0 = (quad & 3) * 4;
        float h[4] = {0.f, 0.f, 0.f, 0.f};
#pragma unroll
        for (int d = 0; d < DD; d++) {
            float xd = sX[bloc][m][d];
#pragma unroll
            for (int j = 0; j < 4; j++) h[j] = fmaf(xd, sW[d][e0 + j], h[j]);
        }
#pragma unroll
        for (int j = 0; j < 4; j++) h[j] = h[j] > 0.f ? h[j] : 0.2f * h[j];

        size_t off = (size_t)(m0 + m) * CC + c0 + quad * 4;
        *reinterpret_cast<float4*>(Hf + off) = make_float4(h[0], h[1], h[2], h[3]);
        union { __nv_bfloat162 p[2]; uint2 u; } pk;
        pk.p[0] = __floats2bfloat162_rn(h[0], h[1]);
        pk.p[1] = __floats2bfloat162_rn(h[2], h[3]);
        *reinterpret_cast<uint2*>(Hb + off) = pk.u;
    }
}

// ===== GEMM + fused next-layer linear (exact R8/R13) =====
__global__ __launch_bounds__(128, 2)
void gemm_fused_kernel(const __nv_bfloat16* __restrict__ Ab,
                       const __nv_bfloat16* __restrict__ Hb_in,
                       const float* __restrict__ Hf_in,
                       const float* __restrict__ Wn,
                       float* __restrict__ Hf_out,
                       __nv_bfloat16* __restrict__ Hb_out,
                       float* __restrict__ Dout,
                       int final_layer) {
    extern __shared__ char dsm[];
    __shared__ float sW[DD][DD + 1];
    const uint32_t sm = smem_u32(dsm);
    const int tid = threadIdx.x, wid = tid >> 5, l = tid & 31;
    const int bx = blockIdx.x, by = blockIdx.y;
    const int wm = wid >> 1, wn = wid & 1;

    if (!final_layer) {
        sW[tid >> 4][tid & 15] = Wn[tid & 255];
        if (tid < 128) sW[(tid + 128) >> 4][tid & 15] = Wn[128 + (tid & 127)];
    }

    const char* gA = (const char*)(Ab + (size_t)by * BM * NN);
    const char* gB = (const char*)Hb_in + (size_t)bx * BN * 2;

    const int rA = tid >> 2, qA = tid & 3;
    uint32_t offA[4]; size_t gOffA[4];
#pragma unroll
    for (int i = 0; i < 4; i++) {
        offA[i]  = swzA(rA + 32 * i, qA);
        gOffA[i] = (size_t)(rA + 32 * i) * 8192 + qA * 16;
    }
    uint32_t offB[4]; int kB[4], qB[4];
#pragma unroll
    for (int i = 0; i < 4; i++) {
        int idx = i * 128 + tid;
        kB[i] = idx >> 4; qB[i] = idx & 15;
        offB[i] = swzB(kB[i], qB[i]);
    }

#define LOAD_STAGE(s, kt) { \
    uint32_t sa = sm + (uint32_t)(s) * STGB; \
    const char* ga = gA + (size_t)(kt) * 64; \
    _Pragma("unroll") \
    for (int i_ = 0; i_ < 4; i_++) cp16(sa + offA[i_], ga + gOffA[i_]); \
    uint32_t sb = sa + ASTG; \
    const char* gb = gB + (size_t)(kt) * 32 * 2048; \
    _Pragma("unroll") \
    for (int i_ = 0; i_ < 4; i_++) \
        cp16(sb + offB[i_], gb + (size_t)kB[i_] * 2048 + qB[i_] * 16); }

    const int arow = wm * 64 + (l & 15);
    const int aqh  = l >> 4;
    const int g    = l >> 3;
    const int bk   = (g & 1) * 8 + (l & 7);
    const int bq   = wn * 8 + (g >> 1);

    float acc[4][8][4];
#pragma unroll
    for (int i = 0; i < 4; i++)
#pragma unroll
        for (int j = 0; j < 8; j++)
#pragma unroll
            for (int k = 0; k < 4; k++) acc[i][j][k] = 0.0f;

#pragma unroll
    for (int s = 0; s < STAGES - 1; s++) {
        LOAD_STAGE(s, s);
        asm volatile("cp.async.commit_group;" ::: "memory");
    }
    asm volatile("cp.async.wait_group %0;" :: "n"(STAGES - 2) : "memory");
    __syncthreads();

    uint32_t a[2][4][4], b[2][4][4];

#pragma unroll 1
    for (int kt = 0; kt < KTILES; kt++) {
        int pf = kt + STAGES - 1;
        if (pf < KTILES) { LOAD_STAGE(pf & (STAGES - 1), pf); }
        asm volatile("cp.async.commit_group;" ::: "memory");

        const uint32_t base  = sm + (uint32_t)(kt & (STAGES - 1)) * STGB;
        const uint32_t baseB = base + ASTG;

#pragma unroll
        for (int mi = 0; mi < 4; mi++)
            LDSM4(a[0][mi], base + swzA(arow + mi * 16, aqh));
#pragma unroll
        for (int nb = 0; nb < 4; nb++)
            LDSM4T(b[0][nb], baseB + swzB(bk, bq + nb * 2));

#pragma unroll
        for (int ks = 0; ks < 2; ks++) {
            if (ks == 0) {
#pragma unroll
                for (int mi = 0; mi < 4; mi++)
                    LDSM4(a[1][mi], base + swzA(arow + mi * 16, 2 + aqh));
#pragma unroll
                for (int nb = 0; nb < 4; nb++)
                    LDSM4T(b[1][nb], baseB + swzB(16 + bk, bq + nb * 2));
            }
#pragma unroll
            for (int mi = 0; mi < 4; mi++) {
#pragma unroll
                for (int nb = 0; nb < 4; nb++) {
                    const uint32_t* bb = b[ks][nb];
                    MMA(acc[mi][2*nb],   a[ks][mi], bb[0], bb[1]);
                    MMA(acc[mi][2*nb+1], a[ks][mi], bb[2], bb[3]);
                }
            }
        }
        asm volatile("cp.async.wait_group %0;" :: "n"(STAGES - 2) : "memory");
        __syncthreads();
    }
    asm volatile("cp.async.wait_group 0;" ::: "memory");
    __syncthreads();

    // ==== epilogue ====
    const int m0g = by * BM, c0g = bx * BN;

    if (final_layer) {
#pragma unroll
        for (int mi = 0; mi < 4; mi++) {
#pragma unroll
            for (int ni = 0; ni < 8; ni++) {
                int m = m0g + wm * 64 + mi * 16 + (l >> 2);
                int c = c0g + wn * 64 + ni * 8 + 2 * (l & 3);
                float2 i0 = *reinterpret_cast<const float2*>(Hf_in + (size_t)m * CC + c);
                float2 i1 = *reinterpret_cast<const float2*>(Hf_in + (size_t)(m + 8) * CC + c);
                float2 o0 = make_float2(acc[mi][ni][0] + i0.x, acc[mi][ni][1] + i0.y);
                float2 o1 = make_float2(acc[mi][ni][2] + i1.x, acc[mi][ni][3] + i1.y);
                int bq2 = c >> 4, d = c & 15;
                *reinterpret_cast<float2*>(Dout + ((size_t)bq2 * NN + m) * DD + d) = o0;
                *reinterpret_cast<float2*>(Dout + ((size_t)bq2 * NN + m + 8) * DD + d) = o1;
            }
        }
        return;
    }

    // stage o = acc + identity into smem [c][m] (pad 129)
    float* stage = reinterpret_cast<float*>(dsm);
#pragma unroll
    for (int mi = 0; mi < 4; mi++) {
#pragma unroll
        for (int ni = 0; ni < 8; ni++) {
            int mloc = wm * 64 + mi * 16 + (l >> 2);
            int cloc = wn * 64 + ni * 8 + 2 * (l & 3);
            int m = m0g + mloc, c = c0g + cloc;
            float2 i0 = *reinterpret_cast<const float2*>(Hf_in + (size_t)m * CC + c);
            float2 i1 = *reinterpret_cast<const float2*>(Hf_in + (size_t)(m + 8) * CC + c);
            stage[cloc * STAGE_PAD + mloc]           = acc[mi][ni][0] + i0.x;
            stage[(cloc + 1) * STAGE_PAD + mloc]     = acc[mi][ni][1] + i0.y;
            stage[cloc * STAGE_PAD + mloc + 8]       = acc[mi][ni][2] + i1.x;
            stage[(cloc + 1) * STAGE_PAD + mloc + 8] = acc[mi][ni][3] + i1.y;
        }
    }
    __syncthreads();

    // next-layer linear
    {
        const int bgrp = tid >> 4, mlane = tid & 15;
#pragma unroll
        for (int it = 0; it < 8; it++) {
            int mloc = mlane + 16 * it;
            float o[16];
#pragma unroll
            for (int d = 0; d < 16; d++)
                o[d] = stage[(bgrp * 16 + d) * STAGE_PAD + mloc];
            float h[16];
#pragma unroll
            for (int e = 0; e < 16; e++) h[e] = 0.0f;
#pragma unroll
            for (int d = 0; d < 16; d++) {
                float od = o[d];
#pragma unroll
                for (int e = 0; e < 16; e++) h[e] = fmaf(od, sW[d][e], h[e]);
            }
#pragma unroll
            for (int e = 0; e < 16; e++) h[e] = h[e] > 0.f ? h[e] : 0.2f * h[e];

            size_t off = (size_t)(m0g + mloc) * CC + c0g + bgrp * 16;
#pragma unroll
            for (int j = 0; j < 4; j++)
                *reinterpret_cast<float4*>(Hf_out + off + j * 4) =
                    make_float4(h[4*j], h[4*j+1], h[4*j+2], h[4*j+3]);
            union { __nv_bfloat162 p[4]; uint4 u; } pk;
#pragma unroll
            for (int j = 0; j < 4; j++) pk.p[j] = __floats2bfloat162_rn(h[2*j], h[2*j+1]);
            *reinterpret_cast<uint4*>(Hb_out + off) = pk.u;
#pragma unroll
            for (int j = 0; j < 4; j++) pk.p[j] = __floats2bfloat162_rn(h[8+2*j], h[9+2*j]);
            *reinterpret_cast<uint4*>(Hb_out + off + 8) = pk.u;
        }
    }
#undef LOAD_STAGE
}

// ================= launch =================
extern "C" void kernel_launch(void* const* d_in, const int* in_sizes, int n_in,
                              void* d_out, int out_size) {
    const float* x   = (const float*)d_in[0];
    const float* adj = (const float*)d_in[1];
    const float* W0  = (const float*)d_in[3];
    const float* W1  = (const float*)d_in[4];
    const float* W2  = (const float*)d_in[5];
    float* out = (float*)d_out;

    float *pHf0, *pHf1;
    __nv_bfloat16 *pHb0, *pHb1, *pAb;
    cudaGetSymbolAddress((void**)&pHf0, g_Hf0);
    cudaGetSymbolAddress((void**)&pHf1, g_Hf1);
    cudaGetSymbolAddress((void**)&pHb0, g_Hb0);
    cudaGetSymbolAddress((void**)&pHb1, g_Hb1);
    cudaGetSymbolAddress((void**)&pAb,  g_adjb);

    cudaFuncSetAttribute(gemm_fused_kernel, cudaFuncAttributeMaxDynamicSharedMemorySize, DSMEM);

    dim3 ggrid(CC / BN, NN / BM);                  // (8, 32) = 256 CTAs

    fused0_kernel<<<6144, 256>>>(adj, pAb, x, W0, pHf0, pHb0);
    gemm_fused_kernel<<<ggrid, 128, DSMEM>>>(pAb, pHb0, pHf0, W1, pHf1, pHb1, nullptr, 0);
    gemm_fused_kernel<<<ggrid, 128, DSMEM>>>(pAb, pHb1, pHf1, W2, pHf0, pHb0, nullptr, 0);
    gemm_fused_kernel<<<ggrid, 128, DSMEM>>>(pAb, pHb0, pHf0, nullptr, nullptr, nullptr, out, 1);
}